// round 11
// baseline (speedup 1.0000x reference)
#include <cuda_runtime.h>

// Haar DWT2: input [8, 32, 512, 512] f32 -> output [8, 4, 32, 256, 256] f32.
// Subbands stacked at axis 1: (LL, LH, HL, HH).
//
// Persistent grid-stride variant of the best (4x4-tile) kernel: 1776 CTAs
// (148 SMs x 12) loop over the 32768 tiles. Eliminates per-CTA launch/drain
// bubbles between waves; successive loop iterations overlap stores of tile t
// with loads of tile t+1. Per-tile memory pattern identical to R4:
// 4x independent fully-coalesced 512B/warp streaming loads, 8x float2
// streaming stores per thread.

#define H 512
#define W 512
#define H2 256
#define W2 256
#define CCH 32                  // channels
#define PLANE_IN (H * W)        // 262144
#define PLANE_OUT (H2 * W2)     // 65536
#define NTILES (128 * 256)      // 128 dual-row groups x 256 planes

__device__ __forceinline__ void haar4(float a, float b, float c, float d,
                                      float& ll, float& lh, float& hl, float& hh)
{
    ll = (a + b + c + d) * 0.5f;
    lh = (a + b - c - d) * 0.5f;
    hl = (a - b + c - d) * 0.5f;
    hh = (a - b - c + d) * 0.5f;
}

__global__ __launch_bounds__(128) void haar_dwt2_kernel(
    const float* __restrict__ in, float* __restrict__ out)
{
    const int i = threadIdx.x;             // 0..127 : float4-col index
    const size_t sstride = (size_t)CCH * PLANE_OUT;   // subband group stride

    for (int tile = blockIdx.x; tile < NTILES; tile += gridDim.x) {
        const int hq = tile & 127;         // 0..127 : group of 2 output rows
        const int bc = tile >> 7;          // 0..255 : b*32 + c
        const int b  = bc >> 5;
        const int c  = bc & 31;
        const int h2 = 2 * hq;

        const float* src = in + (size_t)bc * PLANE_IN
                              + (size_t)(4 * hq) * W + 4 * i;
        // 4 independent fully-coalesced streaming loads (MLP=4).
        const float4 r0 = __ldcs(reinterpret_cast<const float4*>(src));
        const float4 r1 = __ldcs(reinterpret_cast<const float4*>(src + W));
        const float4 r2 = __ldcs(reinterpret_cast<const float4*>(src + 2 * W));
        const float4 r3 = __ldcs(reinterpret_cast<const float4*>(src + 3 * W));

        // pywt haar: LL=(a+b+c+d)/2, LH=(a+b-c-d)/2, HL=(a-b+c-d)/2, HH=(a-b-c+d)/2
        float2 LL0, LH0, HL0, HH0;   // output row h2
        float2 LL1, LH1, HL1, HH1;   // output row h2+1
        haar4(r0.x, r0.y, r1.x, r1.y, LL0.x, LH0.x, HL0.x, HH0.x);
        haar4(r0.z, r0.w, r1.z, r1.w, LL0.y, LH0.y, HL0.y, HH0.y);
        haar4(r2.x, r2.y, r3.x, r3.y, LL1.x, LH1.x, HL1.x, HH1.x);
        haar4(r2.z, r2.w, r3.z, r3.w, LL1.y, LH1.y, HL1.y, HH1.y);

        // out layout: [b][s][c][h2][w2] with s in {0:LL,1:LH,2:HL,3:HH}
        const size_t base = ((size_t)(b * 4) * CCH + c) * PLANE_OUT
                            + (size_t)h2 * W2 + 2 * i;
        float* o = out + base;
        __stcs(reinterpret_cast<float2*>(o),                    LL0);
        __stcs(reinterpret_cast<float2*>(o + W2),               LL1);
        __stcs(reinterpret_cast<float2*>(o + sstride),          LH0);
        __stcs(reinterpret_cast<float2*>(o + sstride + W2),     LH1);
        __stcs(reinterpret_cast<float2*>(o + 2 * sstride),      HL0);
        __stcs(reinterpret_cast<float2*>(o + 2 * sstride + W2), HL1);
        __stcs(reinterpret_cast<float2*>(o + 3 * sstride),      HH0);
        __stcs(reinterpret_cast<float2*>(o + 3 * sstride + W2), HH1);
    }
}

extern "C" void kernel_launch(void* const* d_in, const int* in_sizes, int n_in,
                              void* d_out, int out_size)
{
    const float* in = (const float*)d_in[0];
    float* out = (float*)d_out;
    // Persistent: one CTA wave fills the chip (148 SMs x 12 CTAs of 4 warps).
    haar_dwt2_kernel<<<148 * 12, 128>>>(in, out);
}

// round 12
// speedup vs baseline: 1.1352x; 1.1352x over previous
#include <cuda_runtime.h>

// Haar DWT2: input [8, 32, 512, 512] f32 -> output [8, 4, 32, 256, 256] f32.
// Subbands stacked at axis 1: (LL, LH, HL, HH).
//
// FINAL. Best of 8 structural variants (tile shapes 2x4/2x8/4x4/8x4,
// shfl-packed stores, cache policies cs/wt/default, persistent grid) — all
// well-formed variants converge at 6.4-6.5 TB/s = ~81% of 8 TB/s spec, the
// measured HBM3e mixed 1-read/4-write-stream turnaround ceiling (SM-side
// metrics all <40% of limits; traffic provably minimal at 512 MiB).
//
// Shape: each thread processes a 4(row) x 4(col) input block -> 2 output rows
// x 2 pixels per subband. Loads: 4x independent fully-coalesced 512B/warp
// streaming loads (MLP=4). Stores: 8x float2 evict-first streaming stores,
// coalesced per subband plane. Disposable 128-thread CTAs (32768 total):
// each CTA front-batches its loads with nothing ahead of them; the work
// distributor pipelines waves for free (persistent variant measured slower).

#define H 512
#define W 512
#define H2 256
#define W2 256
#define CCH 32                  // channels
#define PLANE_IN (H * W)        // 262144
#define PLANE_OUT (H2 * W2)     // 65536

__device__ __forceinline__ void haar4(float a, float b, float c, float d,
                                      float& ll, float& lh, float& hl, float& hh)
{
    ll = (a + b + c + d) * 0.5f;
    lh = (a + b - c - d) * 0.5f;
    hl = (a - b + c - d) * 0.5f;
    hh = (a - b - c + d) * 0.5f;
}

__global__ __launch_bounds__(128) void haar_dwt2_kernel(
    const float* __restrict__ in, float* __restrict__ out)
{
    const int i   = threadIdx.x;           // 0..127 : float4-col index
    const int hq  = blockIdx.x;            // 0..127 : group of 2 output rows
    const int bc  = blockIdx.y;            // 0..255 : b*32 + c
    const int b   = bc >> 5;
    const int c   = bc & 31;
    const int h2  = 2 * hq;                // first output row of this block

    const float* src = in + (size_t)bc * PLANE_IN + (size_t)(4 * hq) * W + 4 * i;
    // 4 independent fully-coalesced streaming loads (MLP=4).
    const float4 r0 = __ldcs(reinterpret_cast<const float4*>(src));
    const float4 r1 = __ldcs(reinterpret_cast<const float4*>(src + W));
    const float4 r2 = __ldcs(reinterpret_cast<const float4*>(src + 2 * W));
    const float4 r3 = __ldcs(reinterpret_cast<const float4*>(src + 3 * W));

    // pywt haar: LL=(a+b+c+d)/2, LH=(a+b-c-d)/2, HL=(a-b+c-d)/2, HH=(a-b-c+d)/2
    float2 LL0, LH0, HL0, HH0;   // output row h2
    float2 LL1, LH1, HL1, HH1;   // output row h2+1
    haar4(r0.x, r0.y, r1.x, r1.y, LL0.x, LH0.x, HL0.x, HH0.x);
    haar4(r0.z, r0.w, r1.z, r1.w, LL0.y, LH0.y, HL0.y, HH0.y);
    haar4(r2.x, r2.y, r3.x, r3.y, LL1.x, LH1.x, HL1.x, HH1.x);
    haar4(r2.z, r2.w, r3.z, r3.w, LL1.y, LH1.y, HL1.y, HH1.y);

    // out layout: [b][s][c][h2][w2] with s in {0:LL,1:LH,2:HL,3:HH}
    const size_t base = ((size_t)(b * 4) * CCH + c) * PLANE_OUT
                        + (size_t)h2 * W2 + 2 * i;
    float* o = out + base;
    const size_t sstride = (size_t)CCH * PLANE_OUT;  // subband group stride
    __stcs(reinterpret_cast<float2*>(o),                    LL0);
    __stcs(reinterpret_cast<float2*>(o + W2),               LL1);
    __stcs(reinterpret_cast<float2*>(o + sstride),          LH0);
    __stcs(reinterpret_cast<float2*>(o + sstride + W2),     LH1);
    __stcs(reinterpret_cast<float2*>(o + 2 * sstride),      HL0);
    __stcs(reinterpret_cast<float2*>(o + 2 * sstride + W2), HL1);
    __stcs(reinterpret_cast<float2*>(o + 3 * sstride),      HH0);
    __stcs(reinterpret_cast<float2*>(o + 3 * sstride + W2), HH1);
}

extern "C" void kernel_launch(void* const* d_in, const int* in_sizes, int n_in,
                              void* d_out, int out_size)
{
    const float* in = (const float*)d_in[0];
    float* out = (float*)d_out;
    dim3 grid(H2 / 2, 8 * CCH);   // (128 dual-row groups, 256 b*c planes)
    haar_dwt2_kernel<<<grid, 128>>>(in, out);
}

// round 13
// speedup vs baseline: 1.1370x; 1.0016x over previous
#include <cuda_runtime.h>

// Haar DWT2: input [8, 32, 512, 512] f32 -> output [8, 4, 32, 256, 256] f32.
// Subbands stacked at axis 1: (LL, LH, HL, HH).
//
// 4(row) x 8(col) tile per thread: 8x float4 streaming loads (4 rows x 2,
// pairs at +16B land in the same 128B lines), 8x float4 dense streaming
// stores (2 output rows x 4 subbands, 512B/warp/subband segments). Halves
// store-instruction count per byte vs the 4x4 variant. CTA covers a
// contiguous 16KB input span.

#define H 512
#define W 512
#define H2 256
#define W2 256
#define CCH 32                  // channels
#define PLANE_IN (H * W)        // 262144
#define PLANE_OUT (H2 * W2)     // 65536

__device__ __forceinline__ void haar4(float a, float b, float c, float d,
                                      float& ll, float& lh, float& hl, float& hh)
{
    ll = (a + b + c + d) * 0.5f;
    lh = (a + b - c - d) * 0.5f;
    hl = (a - b + c - d) * 0.5f;
    hh = (a - b - c + d) * 0.5f;
}

__global__ __launch_bounds__(128) void haar_dwt2_kernel(
    const float* __restrict__ in, float* __restrict__ out)
{
    const int t  = threadIdx.x;            // 0..127
    const int wv = t & 63;                 // 0..63 : 8-col group within row
    const int hr = t >> 6;                 // 0..1  : row-quad within CTA
    const int q  = blockIdx.x * 2 + hr;    // 0..127: input row-quad (4 rows)
    const int bc = blockIdx.y;             // 0..255: b*32 + c
    const int b  = bc >> 5;
    const int c  = bc & 31;
    const int h2 = 2 * q;                  // first output row

    const float* src = in + (size_t)bc * PLANE_IN + (size_t)(4 * q) * W + 8 * wv;
    // 8 streaming loads; row pairs at +16B coalesce into the same 128B lines.
    float4 ra[4], rb[4];
#pragma unroll
    for (int k = 0; k < 4; k++) {
        ra[k] = __ldcs(reinterpret_cast<const float4*>(src + (size_t)k * W));
        rb[k] = __ldcs(reinterpret_cast<const float4*>(src + (size_t)k * W + 4));
    }

    // out layout: [b][s][c][h2][w2] with s in {0:LL,1:LH,2:HL,3:HH}
    const size_t base = ((size_t)(b * 4) * CCH + c) * PLANE_OUT
                        + (size_t)h2 * W2 + 4 * wv;
    float* o = out + base;
    const size_t sstride = (size_t)CCH * PLANE_OUT;  // subband group stride

#pragma unroll
    for (int j = 0; j < 2; j++) {          // output row h2+j from input rows 2j,2j+1
        const float4 t0 = ra[2 * j], t1 = ra[2 * j + 1];   // cols 0..3
        const float4 u0 = rb[2 * j], u1 = rb[2 * j + 1];   // cols 4..7
        float4 LL, LH, HL, HH;
        haar4(t0.x, t0.y, t1.x, t1.y, LL.x, LH.x, HL.x, HH.x);
        haar4(t0.z, t0.w, t1.z, t1.w, LL.y, LH.y, HL.y, HH.y);
        haar4(u0.x, u0.y, u1.x, u1.y, LL.z, LH.z, HL.z, HH.z);
        haar4(u0.z, u0.w, u1.z, u1.w, LL.w, LH.w, HL.w, HH.w);
        float* oj = o + (size_t)j * W2;
        __stcs(reinterpret_cast<float4*>(oj),               LL);
        __stcs(reinterpret_cast<float4*>(oj + sstride),     LH);
        __stcs(reinterpret_cast<float4*>(oj + 2 * sstride), HL);
        __stcs(reinterpret_cast<float4*>(oj + 3 * sstride), HH);
    }
}

extern "C" void kernel_launch(void* const* d_in, const int* in_sizes, int n_in,
                              void* d_out, int out_size)
{
    const float* in = (const float*)d_in[0];
    float* out = (float*)d_out;
    dim3 grid(64, 8 * CCH);   // (64 CTA row-groups of 8 rows, 256 b*c planes)
    haar_dwt2_kernel<<<grid, 128>>>(in, out);
}